// round 11
// baseline (speedup 1.0000x reference)
#include <cuda_runtime.h>
#include <math.h>

#define MAXN 100000
#define MAXE 800000

// Scratch (no allocation allowed in kernel_launch).
// Invariant: g_deg and g_sum are all-zero at kernel_launch entry.
//  - first call: __device__ globals are zero-initialized at module load
//  - later calls: k_nodedeg re-zeros g_sum, k_div re-zeros g_deg
__device__ float g_deg[MAXN];        // sum |val| per destination
__device__ float g_sum[MAXN];        // softmax denominator per destination
__device__ float g_feat[MAXN * 32];  // per-node [f@W1_top | f@W1_bot]

__constant__ float cW1[256 * 16];    // W1, copied D2D once per launch

typedef unsigned long long u64;

__device__ __forceinline__ float leaky(float v) {
    return fmaxf(v, 0.1f * v);       // branchless: FMUL + FMNMX
}

// packed fp32x2 ops: per-32-bit-lane fp32 arithmetic in b64 registers
__device__ __forceinline__ void fma2(u64& c, u64 a, u64 b) {
    asm("fma.rn.f32x2 %0, %1, %2, %0;" : "+l"(c) : "l"(a), "l"(b));
}
__device__ __forceinline__ u64 add2(u64 a, u64 b) {
    u64 r;
    asm("add.rn.f32x2 %0, %1, %2;" : "=l"(r) : "l"(a), "l"(b));
    return r;
}
__device__ __forceinline__ u64 pack2(float lo, float hi) {
    u64 r;
    asm("mov.b64 %0, {%1, %2};" : "=l"(r) : "f"(lo), "f"(hi));
    return r;
}
__device__ __forceinline__ float2 unpack2(u64 v) {
    float lo, hi;
    asm("mov.b64 {%0, %1}, %2;" : "=f"(lo), "=f"(hi) : "l"(v));
    return make_float2(lo, hi);
}

// ---------------------------------------------------------------------------
// Kernel 1 (fused, 3 block ranges; 128 threads/block):
//   [0, nodeBlocks)          : projection g[n] = f[n] @ Wcat (64 nodes/block)
//   [nodeBlocks, +degBlocks) : deg[i] += |val[e]|, 4 edges/thread (MLP=4)
//   [.., +sumBlocks)         : g_sum[n] = 0 (restores invariant for k_edge)
//
// Projection dataflow (the wavefront-economy fix):
//   - f staged coalesced into a TRANSPOSED smem tile sFT[k][node], stride 65
//     -> compute reads are dense conflict-free LDS.32 (1 wf serves 32 nodes).
//   - W comes from __constant__ (uniform per warp, constant-cache path,
//     ZERO L1tex wavefronts), pre-packed as col-pair b64 FFMA2 operands.
//   - warp = 32 nodes x 16 cols (lane = node, 8 FFMA2 chains per lane);
//     block = 4 warps = 2 node-groups x 2 col-groups = 64 nodes, all 32 cols.
// ---------------------------------------------------------------------------
__global__ void __launch_bounds__(128) k_nodedeg(
        const float* __restrict__ f,
        const int* __restrict__ ind, const float* __restrict__ val,
        int N, int E, int nodeBlocks, int degBlocks) {
    __shared__ float sFT[128 * 65];  // 33.3 KB: sFT[k*65 + node]

    if (blockIdx.x >= nodeBlocks) {
        int b = blockIdx.x - nodeBlocks;
        if (b < degBlocks) {
            int base = (b * blockDim.x + threadIdx.x) * 4;
            if (base + 3 < E) {
                int4   i4 = *(const int4*)(ind + base);
                float4 v4 = *(const float4*)(val + base);
                atomicAdd(&g_deg[i4.x], fabsf(v4.x));
                atomicAdd(&g_deg[i4.y], fabsf(v4.y));
                atomicAdd(&g_deg[i4.z], fabsf(v4.z));
                atomicAdd(&g_deg[i4.w], fabsf(v4.w));
            } else {
                for (int e = base; e < E; e++)
                    atomicAdd(&g_deg[ind[e]], fabsf(val[e]));
            }
        } else {
            int n = (b - degBlocks) * blockDim.x + threadIdx.x;
            if (n < N) g_sum[n] = 0.f;
        }
        return;
    }

    int tid = threadIdx.x;
    int n0 = blockIdx.x * 64;

    // Stage 64 f rows, transposing into sFT. Warp = one node row (coalesced
    // 512B LDG.128, streaming hint keeps W resident in const/L2 paths);
    // scatter as 4x STS.32 (4-way bank conflict, cold path only).
    const float4* f4 = (const float4*)f;
#pragma unroll
    for (int it = 0; it < 16; it++) {
        int g = it * 128 + tid;           // 0..2047
        int node = g >> 5;                // 0..63
        int c4 = g & 31;                  // k-quad 0..31
        int gn = min(n0 + node, N - 1);
        float4 v = __ldcs(&f4[gn * 32 + c4]);
        sFT[(4 * c4 + 0) * 65 + node] = v.x;
        sFT[(4 * c4 + 1) * 65 + node] = v.y;
        sFT[(4 * c4 + 2) * 65 + node] = v.z;
        sFT[(4 * c4 + 3) * 65 + node] = v.w;
    }
    __syncthreads();

    int warp = tid >> 5;
    int lane = tid & 31;
    int cg = warp & 1;                    // col group: 0 -> cols 0-15, 1 -> 16-31
    int ng = warp >> 1;                   // node group
    int node = ng * 32 + lane;

    u64 acc[8];
#pragma unroll
    for (int p = 0; p < 8; p++) acc[p] = 0ull;

    int krowBase = cg ? 128 : 0;          // Wcat cols 16-31 live in W1 rows 128+k

#pragma unroll 4
    for (int k = 0; k < 128; k++) {
        float fv = sFT[k * 65 + node];    // dense conflict-free LDS.32 (1 wf)
        u64 a = pack2(fv, fv);
        const ulonglong2* cw =
            (const ulonglong2*)&cW1[(krowBase + k) * 16];  // constant path
        ulonglong2 w0 = cw[0];
        ulonglong2 w1 = cw[1];
        fma2(acc[0], a, w0.x);
        fma2(acc[1], a, w0.y);
        fma2(acc[2], a, w1.x);
        fma2(acc[3], a, w1.y);
        ulonglong2 w2 = cw[2];
        ulonglong2 w3 = cw[3];
        fma2(acc[4], a, w2.x);
        fma2(acc[5], a, w2.y);
        fma2(acc[6], a, w3.x);
        fma2(acc[7], a, w3.y);
    }

    int gnode = n0 + node;
    if (gnode < N) {
        float4* dst = (float4*)(g_feat + (size_t)gnode * 32 + cg * 16);
#pragma unroll
        for (int q = 0; q < 4; q++) {
            float2 a = unpack2(acc[2 * q]);
            float2 b = unpack2(acc[2 * q + 1]);
            dst[q] = make_float4(a.x, a.y, b.x, b.y);
        }
    }
}

// ---------------------------------------------------------------------------
// Kernel 2 (fused edge MLP + exp + sum):
//   Phase A: stage edge indices to smem.
//   Phase B: cooperative gather — 8 lanes per edge fetch gi-top/gj-bot float4s.
//   Phase C: thread-per-edge MLP, column-at-a-time vs transposed W2
//            (stride 20 -> weights as 4 broadcast LDS.128, pre-packed pairs),
//            packed f32x2 FMAs/adds. ex=__expf(logit) (softmax shift-
//            invariant, logits O(+-6): no max pass), out[e]=ex, atomic sum[i].
// ---------------------------------------------------------------------------
__global__ void __launch_bounds__(256, 5) k_edge(
        const int* __restrict__ ind, const float* __restrict__ val,
        const float* __restrict__ b1, const float* __restrict__ W2,
        const float* __restrict__ b2, const float* __restrict__ Wc,
        const float* __restrict__ bc, float* __restrict__ out, int E) {
    __shared__ float sX[256 * 34];     // staged [gi_top(16) | gj_bot(16)] per edge
    __shared__ int   sI[256], sJ[256];
    __shared__ float sW2T[17 * 20];    // transposed, stride 20 (16B aligned rows)
    __shared__ float sB1[16], sB2[17], sWc[17];
    __shared__ float sBc;

    int tid = threadIdx.x;
    for (int t = tid; t < 289; t += blockDim.x) {
        int r = t / 17, c = t % 17;
        sW2T[c * 20 + r] = W2[t];
    }
    if (tid < 16) sB1[tid] = b1[tid];
    if (tid >= 32 && tid < 49) sB2[tid - 32] = b2[tid - 32];
    if (tid >= 64 && tid < 81) sWc[tid - 64] = Wc[tid - 64];
    if (tid == 96) sBc = bc[0];

    // Phase A
    int e0 = blockIdx.x * 256;
    int e = e0 + tid;
    bool valid = (e < E);
    sI[tid] = valid ? ind[e] : 0;
    sJ[tid] = valid ? ind[E + e] : 0;
    __syncthreads();

    // Phase B: 2048 float4 gather tasks, 8 per edge
#pragma unroll
    for (int it = 0; it < 8; it++) {
        int t = tid + it * 256;
        int eL = t >> 3;
        int p = t & 7;                              // 0-3: gi row, 4-7: gj row
        int node = (p < 4) ? sI[eL] : sJ[eL];
        float4 v = ((const float4*)(g_feat + (size_t)node * 32))[p];
        float* dst = &sX[eL * 34 + p * 4];          // even offset -> 8B aligned
        ((float2*)dst)[0] = make_float2(v.x, v.y);
        ((float2*)dst)[1] = make_float2(v.z, v.w);
    }
    __syncthreads();

    if (!valid) return;

    int i = sI[tid];
    const u64* sxu = (const u64*)(sX + tid * 34);
    const u64* b1u = (const u64*)sB1;

    // x = leaky(gi_top + gj_bot + b1) via packed adds, packed into 8 b64 pairs
    u64 xp[8];
#pragma unroll
    for (int q = 0; q < 8; q++) {
        u64 s = add2(add2(sxu[q], sxu[8 + q]), b1u[q]);
        float2 v = unpack2(s);
        xp[q] = pack2(leaky(v.x), leaky(v.y));
    }
    float x16 = __fdividef(fabsf(val[e]), g_deg[i]);

    // column-at-a-time second layer + collapse; dual packed partial chains
    float ev0 = sBc, ev1 = 0.f;
#pragma unroll
    for (int c = 0; c < 17; c++) {
        const ulonglong2* wcu = (const ulonglong2*)(sW2T + c * 20);  // broadcast
        u64 accA = 0ull, accB = 0ull;
        ulonglong2 w01 = wcu[0];   // rows 0-3
        ulonglong2 w23 = wcu[1];   // rows 4-7
        ulonglong2 w45 = wcu[2];   // rows 8-11
        ulonglong2 w67 = wcu[3];   // rows 12-15
        fma2(accA, xp[0], w01.x);
        fma2(accB, xp[1], w01.y);
        fma2(accA, xp[2], w23.x);
        fma2(accB, xp[3], w23.y);
        fma2(accA, xp[4], w45.x);
        fma2(accB, xp[5], w45.y);
        fma2(accA, xp[6], w67.x);
        fma2(accB, xp[7], w67.y);
        float2 a = unpack2(accA);
        float2 b = unpack2(accB);
        float yc = leaky((a.x + a.y) + (b.x + b.y)
                         + fmaf(x16, sW2T[c * 20 + 16], sB2[c]));
        if (c & 1) ev1 = fmaf(yc, sWc[c], ev1);
        else       ev0 = fmaf(yc, sWc[c], ev0);
    }

    float ex = __expf(ev0 + ev1);
    out[e] = ex;
    atomicAdd(&g_sum[i], ex);
}

// ---------------------------------------------------------------------------
// Kernel 3: out[e] /= sum[i], 4 edges/thread with coalesced int4/float4 and
// batched gathers (MLP=4). Extra blocks re-zero g_deg for the next replay
// (g_deg is not read here, so no ordering hazard).
// ---------------------------------------------------------------------------
__global__ void k_div(const int* __restrict__ ind, float* __restrict__ out,
                      int E, int edgeBlocks, int N) {
    if (blockIdx.x >= edgeBlocks) {
        int n = (blockIdx.x - edgeBlocks) * blockDim.x + threadIdx.x;
        if (n < N) g_deg[n] = 0.f;
        return;
    }
    int base = (blockIdx.x * blockDim.x + threadIdx.x) * 4;
    if (base + 3 < E) {
        int4   i4 = *(const int4*)(ind + base);
        float4 o4 = *(const float4*)(out + base);
        float s0 = g_sum[i4.x], s1 = g_sum[i4.y];
        float s2 = g_sum[i4.z], s3 = g_sum[i4.w];
        o4.x = __fdividef(o4.x, s0);
        o4.y = __fdividef(o4.y, s1);
        o4.z = __fdividef(o4.z, s2);
        o4.w = __fdividef(o4.w, s3);
        *(float4*)(out + base) = o4;
    } else {
        for (int e = base; e < E; e++)
            out[e] = __fdividef(out[e], g_sum[ind[e]]);
    }
}

// ---------------------------------------------------------------------------
extern "C" void kernel_launch(void* const* d_in, const int* in_sizes, int n_in,
                              void* d_out, int out_size) {
    const int*   ind = (const int*)d_in[0];    // [2, E]
    const float* val = (const float*)d_in[1];  // [E]
    const float* f   = (const float*)d_in[2];  // [N, 128]
    const float* W1  = (const float*)d_in[4];  // [256, 16]
    const float* b1  = (const float*)d_in[5];  // [16]
    const float* W2  = (const float*)d_in[6];  // [17, 17]
    const float* b2  = (const float*)d_in[7];  // [17]
    const float* Wc  = (const float*)d_in[8];  // [17, 1]
    const float* bc  = (const float*)d_in[9];  // [1]
    float* out = (float*)d_out;

    int E = in_sizes[1];
    int N = in_sizes[2] / 128;

    // W1 -> constant bank (D2D async copy: graph-capturable, no allocation)
    void* sym = nullptr;
    cudaGetSymbolAddress(&sym, cW1);
    cudaMemcpyAsync(sym, (const void*)W1, 256 * 16 * sizeof(float),
                    cudaMemcpyDeviceToDevice);

    int tbN = 128;                           // k_nodedeg block size
    int nodeBlocks = (N + 63) / 64;          // 64-node tiles
    int degBlocks = (E + tbN * 4 - 1) / (tbN * 4);   // 4 edges/thread
    int sumBlocks = (N + tbN - 1) / tbN;

    int tb = 256;
    int gE = (E + tb - 1) / tb;              // edge blocks (k_edge)
    int gE4 = (E + tb * 4 - 1) / (tb * 4);   // 4 edges/thread (k_div)
    int gN = (N + tb - 1) / tb;              // node blocks (zeroing)

    k_nodedeg<<<nodeBlocks + degBlocks + sumBlocks, tbN>>>(
        f, ind, val, N, E, nodeBlocks, degBlocks);
    k_edge<<<gE, tb>>>(ind, val, b1, W2, b2, Wc, bc, out, E);
    k_div<<<gE4 + gN, tb>>>(ind, out, E, gE4, N);
}

// round 13
// speedup vs baseline: 1.5019x; 1.5019x over previous
#include <cuda_runtime.h>
#include <math.h>

#define MAXN 100000
#define MAXE 800000

// Scratch (no allocation allowed in kernel_launch).
// Invariant: g_deg and g_sum are all-zero at kernel_launch entry.
//  - first call: __device__ globals are zero-initialized at module load
//  - later calls: k_nodedeg re-zeros g_sum, k_div re-zeros g_deg
__device__ float g_deg[MAXN];        // sum |val| per destination
__device__ float g_sum[MAXN];        // softmax denominator per destination
__device__ float g_feat[MAXN * 32];  // per-node [f@W1_top | f@W1_bot]

typedef unsigned long long u64;

__device__ __forceinline__ float leaky(float v) {
    return fmaxf(v, 0.1f * v);       // branchless: FMUL + FMNMX
}

// packed fp32x2 ops: per-32-bit-lane fp32 arithmetic in b64 registers
__device__ __forceinline__ void fma2(u64& c, u64 a, u64 b) {
    asm("fma.rn.f32x2 %0, %1, %2, %0;" : "+l"(c) : "l"(a), "l"(b));
}
__device__ __forceinline__ u64 add2(u64 a, u64 b) {
    u64 r;
    asm("add.rn.f32x2 %0, %1, %2;" : "=l"(r) : "l"(a), "l"(b));
    return r;
}
__device__ __forceinline__ u64 pack2(float lo, float hi) {
    u64 r;
    asm("mov.b64 %0, {%1, %2};" : "=l"(r) : "f"(lo), "f"(hi));
    return r;
}
__device__ __forceinline__ float2 unpack2(u64 v) {
    float lo, hi;
    asm("mov.b64 {%0, %1}, %2;" : "=f"(lo), "=f"(hi) : "l"(v));
    return make_float2(lo, hi);
}

// ---------------------------------------------------------------------------
// Kernel 1 (fused, 3 block ranges):
//   [0, nodeBlocks)          : projection g[n] = f[n] @ Wcat, 64-node tiles
//   [nodeBlocks, +degBlocks) : deg[i] += |val[e]|, 4 edges/thread (MLP=4)
//   [.., +sumBlocks)         : g_sum[n] = 0 (restores invariant for k_edge)
//
// Projection (R8 structure — measured local optimum of the crossbar):
//   f tile staged to smem coalesced; compute reads f as broadcast LDS.128
//   and W as one divergent conflict-free LDS.128 per k-quad amortized over
//   8 nodes per warp. All FMAs are packed fma.rn.f32x2.
// ---------------------------------------------------------------------------
__global__ void __launch_bounds__(256, 4) k_nodedeg(
        const float* __restrict__ f, const float* __restrict__ W1,
        const int* __restrict__ ind, const float* __restrict__ val,
        int N, int E, int nodeBlocks, int degBlocks) {
    __shared__ float sW[128 * 32];   // 16 KB
    __shared__ float sF[64 * 128];   // 32 KB: 64-node f tile

    if (blockIdx.x >= nodeBlocks) {
        int b = blockIdx.x - nodeBlocks;
        if (b < degBlocks) {
            int base = (b * blockDim.x + threadIdx.x) * 4;
            if (base + 3 < E) {
                int4   i4 = *(const int4*)(ind + base);
                float4 v4 = *(const float4*)(val + base);
                atomicAdd(&g_deg[i4.x], fabsf(v4.x));
                atomicAdd(&g_deg[i4.y], fabsf(v4.y));
                atomicAdd(&g_deg[i4.z], fabsf(v4.z));
                atomicAdd(&g_deg[i4.w], fabsf(v4.w));
            } else {
                for (int e = base; e < E; e++)
                    atomicAdd(&g_deg[ind[e]], fabsf(val[e]));
            }
        } else {
            int n = (b - degBlocks) * blockDim.x + threadIdx.x;
            if (n < N) g_sum[n] = 0.f;
        }
        return;
    }

    // sW[(k>>2)*128 + c*4 + (k&3)] = Wcat[k][c],
    // Wcat[k][c] = (c<16) ? W1[k][c] : W1[128+k][c-16]
    for (int t = threadIdx.x; t < 128 * 32; t += blockDim.x) {
        int kq = t >> 7;
        int rem = t & 127;
        int c = rem >> 2;
        int kl = rem & 3;
        int k = kq * 4 + kl;
        sW[t] = (c < 16) ? W1[k * 16 + c] : W1[(128 + k) * 16 + (c - 16)];
    }

    // Stage f tile: 64 rows x 128 floats = 2048 float4, 8 per thread.
    // Lanes of a warp cover one contiguous row (512 B) -> perfectly coalesced.
    int n0 = blockIdx.x * 64;
    float4* sF4w = (float4*)sF;
#pragma unroll
    for (int it = 0; it < 8; it++) {
        int idx = threadIdx.x + it * 256;     // 0..2047
        int row = idx >> 5;                   // 0..63
        int c4  = idx & 31;                   // 0..31
        int n = min(n0 + row, N - 1);
        sF4w[row * 32 + c4] = ((const float4*)(f + (size_t)n * 128))[c4];
    }
    __syncthreads();

    int warp = threadIdx.x >> 5;
    int lane = threadIdx.x & 31;
    int base = warp * 8;                      // local node row of this warp

    const ulonglong2* sWp = (const ulonglong2*)sW;   // LDS.128 -> 2 packed pairs
    const ulonglong2* sFp = (const ulonglong2*)sF;

    u64 acc[8];
#pragma unroll
    for (int q = 0; q < 8; q++) acc[q] = 0ull;

#pragma unroll 8
    for (int kq = 0; kq < 32; kq++) {
        ulonglong2 w = sWp[kq * 32 + lane];   // divergent, conflict-free
#pragma unroll
        for (int q = 0; q < 8; q++) {
            ulonglong2 v = sFp[(base + q) * 32 + kq];   // warp-broadcast
            fma2(acc[q], v.x, w.x);           // 8 independent 2-step chains
            fma2(acc[q], v.y, w.y);
        }
    }

#pragma unroll
    for (int q = 0; q < 8; q++) {
        int n = n0 + base + q;
        float2 r = unpack2(acc[q]);
        if (n < N) g_feat[(size_t)n * 32 + lane] = r.x + r.y;
    }
}

// ---------------------------------------------------------------------------
// Kernel 2 (fused edge MLP + exp + sum):
//   Phase A: stage edge indices to smem.
//   Phase B: cooperative gather — 8 lanes per edge fetch gi-top/gj-bot float4s.
//   Phase C: thread-per-edge MLP, column-at-a-time vs transposed W2
//            (stride 20 -> weights as 4 broadcast LDS.128, pre-packed pairs),
//            packed f32x2 FMAs/adds. ex=__expf(logit) (softmax shift-
//            invariant, logits O(+-6): no max pass), out[e]=ex, atomic sum[i].
// ---------------------------------------------------------------------------
__global__ void __launch_bounds__(256, 5) k_edge(
        const int* __restrict__ ind, const float* __restrict__ val,
        const float* __restrict__ b1, const float* __restrict__ W2,
        const float* __restrict__ b2, const float* __restrict__ Wc,
        const float* __restrict__ bc, float* __restrict__ out, int E) {
    __shared__ float sX[256 * 34];     // staged [gi_top(16) | gj_bot(16)] per edge
    __shared__ int   sI[256], sJ[256];
    __shared__ float sW2T[17 * 20];    // transposed, stride 20 (16B aligned rows)
    __shared__ float sB1[16], sB2[17], sWc[17];
    __shared__ float sBc;

    int tid = threadIdx.x;
    for (int t = tid; t < 289; t += blockDim.x) {
        int r = t / 17, c = t % 17;
        sW2T[c * 20 + r] = W2[t];
    }
    if (tid < 16) sB1[tid] = b1[tid];
    if (tid >= 32 && tid < 49) sB2[tid - 32] = b2[tid - 32];
    if (tid >= 64 && tid < 81) sWc[tid - 64] = Wc[tid - 64];
    if (tid == 96) sBc = bc[0];

    // Phase A
    int e0 = blockIdx.x * 256;
    int e = e0 + tid;
    bool valid = (e < E);
    sI[tid] = valid ? ind[e] : 0;
    sJ[tid] = valid ? ind[E + e] : 0;
    __syncthreads();

    // Phase B: 2048 float4 gather tasks, 8 per edge
#pragma unroll
    for (int it = 0; it < 8; it++) {
        int t = tid + it * 256;
        int eL = t >> 3;
        int p = t & 7;                              // 0-3: gi row, 4-7: gj row
        int node = (p < 4) ? sI[eL] : sJ[eL];
        float4 v = ((const float4*)(g_feat + (size_t)node * 32))[p];
        float* dst = &sX[eL * 34 + p * 4];          // even offset -> 8B aligned
        ((float2*)dst)[0] = make_float2(v.x, v.y);
        ((float2*)dst)[1] = make_float2(v.z, v.w);
    }
    __syncthreads();

    if (!valid) return;

    int i = sI[tid];
    const u64* sxu = (const u64*)(sX + tid * 34);
    const u64* b1u = (const u64*)sB1;

    // x = leaky(gi_top + gj_bot + b1) via packed adds, packed into 8 b64 pairs
    u64 xp[8];
#pragma unroll
    for (int q = 0; q < 8; q++) {
        u64 s = add2(add2(sxu[q], sxu[8 + q]), b1u[q]);
        float2 v = unpack2(s);
        xp[q] = pack2(leaky(v.x), leaky(v.y));
    }
    float x16 = __fdividef(fabsf(val[e]), g_deg[i]);

    // column-at-a-time second layer + collapse; dual packed partial chains
    float ev0 = sBc, ev1 = 0.f;
#pragma unroll
    for (int c = 0; c < 17; c++) {
        const ulonglong2* wcu = (const ulonglong2*)(sW2T + c * 20);  // broadcast
        u64 accA = 0ull, accB = 0ull;
        ulonglong2 w01 = wcu[0];   // rows 0-3
        ulonglong2 w23 = wcu[1];   // rows 4-7
        ulonglong2 w45 = wcu[2];   // rows 8-11
        ulonglong2 w67 = wcu[3];   // rows 12-15
        fma2(accA, xp[0], w01.x);
        fma2(accB, xp[1], w01.y);
        fma2(accA, xp[2], w23.x);
        fma2(accB, xp[3], w23.y);
        fma2(accA, xp[4], w45.x);
        fma2(accB, xp[5], w45.y);
        fma2(accA, xp[6], w67.x);
        fma2(accB, xp[7], w67.y);
        float2 a = unpack2(accA);
        float2 b = unpack2(accB);
        float yc = leaky((a.x + a.y) + (b.x + b.y)
                         + fmaf(x16, sW2T[c * 20 + 16], sB2[c]));
        if (c & 1) ev1 = fmaf(yc, sWc[c], ev1);
        else       ev0 = fmaf(yc, sWc[c], ev0);
    }

    float ex = __expf(ev0 + ev1);
    out[e] = ex;
    atomicAdd(&g_sum[i], ex);
}

// ---------------------------------------------------------------------------
// Kernel 3: out[e] /= sum[i], 4 edges/thread with coalesced int4/float4 and
// batched gathers (MLP=4). Extra blocks re-zero g_deg for the next replay
// (g_deg is not read here, so no ordering hazard).
// ---------------------------------------------------------------------------
__global__ void k_div(const int* __restrict__ ind, float* __restrict__ out,
                      int E, int edgeBlocks, int N) {
    if (blockIdx.x >= edgeBlocks) {
        int n = (blockIdx.x - edgeBlocks) * blockDim.x + threadIdx.x;
        if (n < N) g_deg[n] = 0.f;
        return;
    }
    int base = (blockIdx.x * blockDim.x + threadIdx.x) * 4;
    if (base + 3 < E) {
        int4   i4 = *(const int4*)(ind + base);
        float4 o4 = *(const float4*)(out + base);
        float s0 = g_sum[i4.x], s1 = g_sum[i4.y];
        float s2 = g_sum[i4.z], s3 = g_sum[i4.w];
        o4.x = __fdividef(o4.x, s0);
        o4.y = __fdividef(o4.y, s1);
        o4.z = __fdividef(o4.z, s2);
        o4.w = __fdividef(o4.w, s3);
        *(float4*)(out + base) = o4;
    } else {
        for (int e = base; e < E; e++)
            out[e] = __fdividef(out[e], g_sum[ind[e]]);
    }
}

// ---------------------------------------------------------------------------
extern "C" void kernel_launch(void* const* d_in, const int* in_sizes, int n_in,
                              void* d_out, int out_size) {
    const int*   ind = (const int*)d_in[0];    // [2, E]
    const float* val = (const float*)d_in[1];  // [E]
    const float* f   = (const float*)d_in[2];  // [N, 128]
    const float* W1  = (const float*)d_in[4];  // [256, 16]
    const float* b1  = (const float*)d_in[5];  // [16]
    const float* W2  = (const float*)d_in[6];  // [17, 17]
    const float* b2  = (const float*)d_in[7];  // [17]
    const float* Wc  = (const float*)d_in[8];  // [17, 1]
    const float* bc  = (const float*)d_in[9];  // [1]
    float* out = (float*)d_out;

    int E = in_sizes[1];
    int N = in_sizes[2] / 128;

    int tb = 256;
    int gN = (N + tb - 1) / tb;              // node-count blocks (zeroing)
    int gE = (E + tb - 1) / tb;              // edge blocks (k_edge)
    int gE4 = (E + tb * 4 - 1) / (tb * 4);   // 4 edges/thread blocks
    int nodeBlocks = (N + 63) / 64;          // 64-node tiles

    k_nodedeg<<<nodeBlocks + gE4 + gN, tb>>>(f, W1, ind, val, N, E, nodeBlocks, gE4);
    k_edge<<<gE, tb>>>(ind, val, b1, W2, b2, Wc, bc, out, E);
    k_div<<<gE4 + gN, tb>>>(ind, out, E, gE4, N);
}

// round 16
// speedup vs baseline: 1.6674x; 1.1102x over previous
#include <cuda_runtime.h>
#include <math.h>

#define MAXN 100000
#define MAXE 800000

// Scratch (no allocation allowed in kernel_launch).
// Invariant: g_deg and g_sum are all-zero at kernel_launch entry.
//  - first call: __device__ globals are zero-initialized at module load
//  - later calls: k_nodedeg re-zeros g_sum, k_div re-zeros g_deg
__device__ float g_deg[MAXN];        // sum |val| per destination
__device__ float g_sum[MAXN];        // softmax denominator per destination
__device__ float g_feat[MAXN * 32];  // per-node [f@W1_top | f@W1_bot]

typedef unsigned long long u64;

__device__ __forceinline__ float leaky(float v) {
    return fmaxf(v, 0.1f * v);       // branchless: FMUL + FMNMX
}

// packed fp32x2 ops: per-32-bit-lane fp32 arithmetic in b64 registers
__device__ __forceinline__ void fma2(u64& c, u64 a, u64 b) {
    asm("fma.rn.f32x2 %0, %1, %2, %0;" : "+l"(c) : "l"(a), "l"(b));
}
__device__ __forceinline__ u64 add2(u64 a, u64 b) {
    u64 r;
    asm("add.rn.f32x2 %0, %1, %2;" : "=l"(r) : "l"(a), "l"(b));
    return r;
}
__device__ __forceinline__ u64 pack2(float lo, float hi) {
    u64 r;
    asm("mov.b64 %0, {%1, %2};" : "=l"(r) : "f"(lo), "f"(hi));
    return r;
}
__device__ __forceinline__ float2 unpack2(u64 v) {
    float lo, hi;
    asm("mov.b64 {%0, %1}, %2;" : "=f"(lo), "=f"(hi) : "l"(v));
    return make_float2(lo, hi);
}

// ---------------------------------------------------------------------------
// Kernel 1 (fused, 3 block ranges):
//   [0, nodeBlocks)          : projection g[n] = f[n] @ Wcat, 64-node tiles
//   [nodeBlocks, +degBlocks) : deg[i] += |val[e]|, 4 edges/thread (MLP=4)
//   [.., +sumBlocks)         : g_sum[n] = 0 (restores invariant for k_edge)
//
// Projection: wavefront-optimal tiling. Warp tile = 32 nodes x 16 cols,
// lane tile = 4 nodes (strided: ng + 8i) x 4 cols. f reads are LDS.128 over
// 8 DISTINCT node rows per instr (full 128B wavefront; XOR swizzle
// p = kq ^ (node&7) keeps them bank-conflict-free at stride 128).
// W reads are LDS.128 with 4 distinct 16B chunks x 4-way broadcast.
// 8 warps = 2 node-halves x 2 col-halves x 2 k-halves; k-halves reduced
// via smem (sAcc overlays sW after compute).
// ---------------------------------------------------------------------------
__global__ void __launch_bounds__(256) k_nodedeg(
        const float* __restrict__ f, const float* __restrict__ W1,
        const int* __restrict__ ind, const float* __restrict__ val,
        int N, int E, int nodeBlocks, int degBlocks) {
    __shared__ float sW[128 * 32];   // 16 KB: Wcat[k][c] row-major (later sAcc)
    __shared__ float sF[64 * 128];   // 32 KB: f tile, k-quad-swizzled rows

    if (blockIdx.x >= nodeBlocks) {
        int b = blockIdx.x - nodeBlocks;
        if (b < degBlocks) {
            int base = (b * blockDim.x + threadIdx.x) * 4;
            if (base + 3 < E) {
                int4   i4 = *(const int4*)(ind + base);
                float4 v4 = *(const float4*)(val + base);
                atomicAdd(&g_deg[i4.x], fabsf(v4.x));
                atomicAdd(&g_deg[i4.y], fabsf(v4.y));
                atomicAdd(&g_deg[i4.z], fabsf(v4.z));
                atomicAdd(&g_deg[i4.w], fabsf(v4.w));
            } else {
                for (int e = base; e < E; e++)
                    atomicAdd(&g_deg[ind[e]], fabsf(val[e]));
            }
        } else {
            int n = (b - degBlocks) * blockDim.x + threadIdx.x;
            if (n < N) g_sum[n] = 0.f;
        }
        return;
    }

    int tid = threadIdx.x;
    int n0 = blockIdx.x * 64;

    // Wcat[k][c] = (c<16) ? W1[k][c] : W1[128+k][c-16], row-major 32 per k
    for (int t = tid; t < 128 * 32; t += blockDim.x) {
        int k = t >> 5;
        int c = t & 31;
        sW[t] = (c < 16) ? W1[k * 16 + c] : W1[(128 + k) * 16 + (c - 16)];
    }

    // Stage f: 64 rows, warp per 4 rows, lane l holds k-quad l, stored at
    // swizzled physical quad (l ^ (row&7)). Coalesced LDG.128; STS.128 at
    // the 4-wf minimum.
    {
        int warp = tid >> 5;
        int lane = tid & 31;
        float4* sF4w = (float4*)sF;
        const float4* f4 = (const float4*)f;
#pragma unroll
        for (int r = 0; r < 8; r += 2) {
            int row = warp * 8 + r + (lane >> 4);       // wait-free split? no:
        }
        // simple: 8 warps x 8 rows each
#pragma unroll
        for (int r = 0; r < 8; r++) {
            int row = warp * 8 + r;
            int gn = min(n0 + row, N - 1);
            float4 v = f4[(size_t)gn * 32 + lane];
            sF4w[row * 32 + (lane ^ (row & 7))] = v;
        }
    }
    __syncthreads();

    int warp = tid >> 5;
    int lane = tid & 31;
    int ng = lane >> 2;              // 0..7  (node sub-index)
    int cg = lane & 3;               // 0..3  (col quad within 16-col half)
    int q  = warp >> 2;              // k-half 0/1 (64 k each)
    int ch = (warp >> 1) & 1;        // col-half 0/1
    int nh = warp & 1;               // node-half 0/1

    const float4* sF4 = (const float4*)sF;

    u64 acc[4][2];                   // 4 nodes x 4 cols
#pragma unroll
    for (int i = 0; i < 4; i++) { acc[i][0] = 0ull; acc[i][1] = 0ull; }

    int wofs = ch * 16 + cg * 4;     // float offset of this lane's col quad

#pragma unroll 4
    for (int kq = 0; kq < 16; kq++) {
        int kqi = q * 16 + kq;       // global k-quad 0..31
        float4 fq[4];
#pragma unroll
        for (int i = 0; i < 4; i++) {
            int node = nh * 32 + ng + 8 * i;
            fq[i] = sF4[node * 32 + (kqi ^ ng)];   // 8 distinct rows, 1 wf
        }
#pragma unroll
        for (int j = 0; j < 4; j++) {
            int k = kqi * 4 + j;
            ulonglong2 w = *(const ulonglong2*)(sW + k * 32 + wofs);
#pragma unroll
            for (int i = 0; i < 4; i++) {
                float fv = (j == 0) ? fq[i].x : (j == 1) ? fq[i].y
                         : (j == 2) ? fq[i].z : fq[i].w;
                u64 a = pack2(fv, fv);
                fma2(acc[i][0], a, w.x);
                fma2(acc[i][1], a, w.y);
            }
        }
    }

    // k-half reduction through sAcc (overlays sW; stride 36 floats = 16B
    // aligned, conflict-minimal). Then cooperative coalesced STG.
    float* sAcc = sW;
    __syncthreads();                 // all warps done reading sW/sF
    if (q == 0) {
#pragma unroll
        for (int i = 0; i < 4; i++) {
            int node = nh * 32 + ng + 8 * i;
            float2 a = unpack2(acc[i][0]);
            float2 b = unpack2(acc[i][1]);
            *(float4*)(sAcc + node * 36 + wofs) = make_float4(a.x, a.y, b.x, b.y);
        }
    }
    __syncthreads();
    if (q == 1) {
#pragma unroll
        for (int i = 0; i < 4; i++) {
            int node = nh * 32 + ng + 8 * i;
            float4* p = (float4*)(sAcc + node * 36 + wofs);
            float4 o = *p;
            float2 a = unpack2(acc[i][0]);
            float2 b = unpack2(acc[i][1]);
            *p = make_float4(o.x + a.x, o.y + a.y, o.z + b.x, o.w + b.y);
        }
    }
    __syncthreads();
#pragma unroll
    for (int p2 = 0; p2 < 2; p2++) {
        int idx = tid + p2 * 256;    // 0..511
        int node = idx >> 3;
        int cq = idx & 7;
        int gn = n0 + node;
        if (gn < N)
            *(float4*)(g_feat + (size_t)gn * 32 + 4 * cq) =
                *(const float4*)(sAcc + node * 36 + 4 * cq);
    }
}

// ---------------------------------------------------------------------------
// Kernel 2 (fused edge MLP + exp + sum):
//   Phase A: stage edge indices to smem.
//   Phase B: cooperative gather — 8 lanes per edge fetch gi-top/gj-bot float4s.
//   Phase C: thread-per-edge MLP, column-at-a-time vs transposed W2
//            (stride 20 -> weights as 4 broadcast LDS.128, pre-packed pairs),
//            packed f32x2 FMAs/adds. ex=__expf(logit) (softmax shift-
//            invariant, logits O(+-6): no max pass), out[e]=ex, atomic sum[i].
// ---------------------------------------------------------------------------
__global__ void __launch_bounds__(256, 5) k_edge(
        const int* __restrict__ ind, const float* __restrict__ val,
        const float* __restrict__ b1, const float* __restrict__ W2,
        const float* __restrict__ b2, const float* __restrict__ Wc,
        const float* __restrict__ bc, float* __restrict__ out, int E) {
    __shared__ float sX[256 * 34];     // staged [gi_top(16) | gj_bot(16)] per edge
    __shared__ int   sI[256], sJ[256];
    __shared__ float sW2T[17 * 20];    // transposed, stride 20 (16B aligned rows)
    __shared__ float sB1[16], sB2[17], sWc[17];
    __shared__ float sBc;

    int tid = threadIdx.x;
    for (int t = tid; t < 289; t += blockDim.x) {
        int r = t / 17, c = t % 17;
        sW2T[c * 20 + r] = W2[t];
    }
    if (tid < 16) sB1[tid] = b1[tid];
    if (tid >= 32 && tid < 49) sB2[tid - 32] = b2[tid - 32];
    if (tid >= 64 && tid < 81) sWc[tid - 64] = Wc[tid - 64];
    if (tid == 96) sBc = bc[0];

    // Phase A
    int e0 = blockIdx.x * 256;
    int e = e0 + tid;
    bool valid = (e < E);
    sI[tid] = valid ? ind[e] : 0;
    sJ[tid] = valid ? ind[E + e] : 0;
    __syncthreads();

    // Phase B: 2048 float4 gather tasks, 8 per edge
#pragma unroll
    for (int it = 0; it < 8; it++) {
        int t = tid + it * 256;
        int eL = t >> 3;
        int p = t & 7;                              // 0-3: gi row, 4-7: gj row
        int node = (p < 4) ? sI[eL] : sJ[eL];
        float4 v = ((const float4*)(g_feat + (size_t)node * 32))[p];
        float* dst = &sX[eL * 34 + p * 4];          // even offset -> 8B aligned
        ((float2*)dst)[0] = make_float2(v.x, v.y);
        ((float2*)dst)[1] = make_float2(v.z, v.w);
    }
    __syncthreads();

    if (!valid) return;

    int i = sI[tid];
    const u64* sxu = (const u64*)(sX + tid * 34);
    const u64* b1u = (const u64*)sB1;

    // x = leaky(gi_top + gj_bot + b1) via packed adds, packed into 8 b64 pairs
    u64 xp[8];
#pragma unroll
    for (int q = 0; q < 8; q++) {
        u64 s = add2(add2(sxu[q], sxu[8 + q]), b1u[q]);
        float2 v = unpack2(s);
        xp[q] = pack2(leaky(v.x), leaky(v.y));
    }
    float x16 = __fdividef(fabsf(val[e]), g_deg[i]);

    // column-at-a-time second layer + collapse; dual packed partial chains
    float ev0 = sBc, ev1 = 0.f;
#pragma unroll
    for (int c = 0; c < 17; c++) {
        const ulonglong2* wcu = (const ulonglong2*)(sW2T + c * 20);  // broadcast
        u64 accA = 0ull, accB = 0ull;
        ulonglong2 w01 = wcu[0];   // rows 0-3
        ulonglong2 w23 = wcu[1];   // rows 4-7
        ulonglong2 w45 = wcu[2];   // rows 8-11
        ulonglong2 w67 = wcu[3];   // rows 12-15
        fma2(accA, xp[0], w01.x);
        fma2(accB, xp[1], w01.y);
        fma2(accA, xp[2], w23.x);
        fma2(accB, xp[3], w23.y);
        fma2(accA, xp[4], w45.x);
        fma2(accB, xp[5], w45.y);
        fma2(accA, xp[6], w67.x);
        fma2(accB, xp[7], w67.y);
        float2 a = unpack2(accA);
        float2 b = unpack2(accB);
        float yc = leaky((a.x + a.y) + (b.x + b.y)
                         + fmaf(x16, sW2T[c * 20 + 16], sB2[c]));
        if (c & 1) ev1 = fmaf(yc, sWc[c], ev1);
        else       ev0 = fmaf(yc, sWc[c], ev0);
    }

    float ex = __expf(ev0 + ev1);
    out[e] = ex;
    atomicAdd(&g_sum[i], ex);
}

// ---------------------------------------------------------------------------
// Kernel 3: out[e] /= sum[i], 4 edges/thread with coalesced int4/float4 and
// batched gathers (MLP=4). Extra blocks re-zero g_deg for the next replay
// (g_deg is not read here, so no ordering hazard).
// ---------------------------------------------------------------------------
__global__ void k_div(const int* __restrict__ ind, float* __restrict__ out,
                      int E, int edgeBlocks, int N) {
    if (blockIdx.x >= edgeBlocks) {
        int n = (blockIdx.x - edgeBlocks) * blockDim.x + threadIdx.x;
        if (n < N) g_deg[n] = 0.f;
        return;
    }
    int base = (blockIdx.x * blockDim.x + threadIdx.x) * 4;
    if (base + 3 < E) {
        int4   i4 = *(const int4*)(ind + base);
        float4 o4 = *(const float4*)(out + base);
        float s0 = g_sum[i4.x], s1 = g_sum[i4.y];
        float s2 = g_sum[i4.z], s3 = g_sum[i4.w];
        o4.x = __fdividef(o4.x, s0);
        o4.y = __fdividef(o4.y, s1);
        o4.z = __fdividef(o4.z, s2);
        o4.w = __fdividef(o4.w, s3);
        *(float4*)(out + base) = o4;
    } else {
        for (int e = base; e < E; e++)
            out[e] = __fdividef(out[e], g_sum[ind[e]]);
    }
}

// ---------------------------------------------------------------------------
extern "C" void kernel_launch(void* const* d_in, const int* in_sizes, int n_in,
                              void* d_out, int out_size) {
    const int*   ind = (const int*)d_in[0];    // [2, E]
    const float* val = (const float*)d_in[1];  // [E]
    const float* f   = (const float*)d_in[2];  // [N, 128]
    const float* W1  = (const float*)d_in[4];  // [256, 16]
    const float* b1  = (const float*)d_in[5];  // [16]
    const float* W2  = (const float*)d_in[6];  // [17, 17]
    const float* b2  = (const float*)d_in[7];  // [17]
    const float* Wc  = (const float*)d_in[8];  // [17, 1]
    const float* bc  = (const float*)d_in[9];  // [1]
    float* out = (float*)d_out;

    int E = in_sizes[1];
    int N = in_sizes[2] / 128;

    int tb = 256;
    int gN = (N + tb - 1) / tb;              // node-count blocks (zeroing)
    int gE = (E + tb - 1) / tb;              // edge blocks (k_edge)
    int gE4 = (E + tb * 4 - 1) / (tb * 4);   // 4 edges/thread blocks
    int nodeBlocks = (N + 63) / 64;          // 64-node tiles

    k_nodedeg<<<nodeBlocks + gE4 + gN, tb>>>(f, W1, ind, val, N, E, nodeBlocks, gE4);
    k_edge<<<gE, tb>>>(ind, val, b1, W2, b2, Wc, bc, out, E);
    k_div<<<gE4 + gN, tb>>>(ind, out, E, gE4, N);
}